// round 4
// baseline (speedup 1.0000x reference)
#include <cuda_runtime.h>
#include <math.h>

// ---------------------------------------------------------------------------
// Shapes (fixed for this problem):
//   x: [8,3,128,128]; encoder spatial 64x64 after conv0 (s2).
//   B=8, H=W=64, BH = B*H = 512 row-blocks.
// ---------------------------------------------------------------------------

#define BH 512

// ------------------------------- scratch -----------------------------------
__device__ float g_bufA[16777216];   // [8,512,64,64]
__device__ float g_bufB[16777216];   // [8,512,64,64]
__device__ float g_bufT[4194304];    // [8,128,64,64]
__device__ float g_bufZ[8388608];    // [8,256,64,64]

__device__ float g_pw1 [1179648];    // conv1  packed [9][256][512]
__device__ float g_pw2 [2359296];    // conv2  packed [9][512][512]
__device__ float g_pwE1[9437184];    // enc res w1 packed [16][9][512][128]
__device__ float g_pwE2[1048576];    // enc res w2 packed [16][128][512]
__device__ float g_pw3 [1179648];    // conv3  packed [9][512][256]
__device__ float g_pwD0[1179648];    // dec conv0 packed [9][256][512]
__device__ float g_pwDr1[9437184];   // dec res w1 packed
__device__ float g_pwDr2[1048576];   // dec res w2 packed
__device__ float g_pwD1[1179648];    // dec conv1 packed [9][512][256]
__device__ float g_cbT [262144];     // codebook^T [256][1024]
__device__ float g_cnorm[1024];
__device__ float g_znorm[32768];
__device__ unsigned long long g_bestkey[32768];
__device__ float g_bnscale[512];
__device__ float g_bnshift[512];
__device__ float g_vqsum;
__device__ float g_reconsum;

// ---------------------------- small helpers --------------------------------
__device__ __forceinline__ float warpReduceSum(float v) {
#pragma unroll
    for (int s = 16; s > 0; s >>= 1) v += __shfl_down_sync(0xffffffffu, v, s);
    return v;
}

// ------------------------------ pack kernels -------------------------------
// src: [blk][Cout][Cin][3][3]  ->  dst: [blk][9][Cin][Cout]
__global__ void pack3x3_k(const float* __restrict__ src, float* __restrict__ dst,
                          int nblk, int Cin, int Cout) {
    long long total = (long long)nblk * Cout * Cin * 9;
    for (long long i = (long long)blockIdx.x * blockDim.x + threadIdx.x; i < total;
         i += (long long)gridDim.x * blockDim.x) {
        int r = (int)(i % 9);
        long long t = i / 9;
        int ci = (int)(t % Cin); t /= Cin;
        int co = (int)(t % Cout);
        int blk = (int)(t / Cout);
        dst[(((long long)blk * 9 + r) * Cin + ci) * Cout + co] = src[i];
    }
}

// src: [blk][Cout][Cin]  ->  dst: [blk][Cin][Cout]
__global__ void pack1x1_k(const float* __restrict__ src, float* __restrict__ dst,
                          int nblk, int Cin, int Cout) {
    long long total = (long long)nblk * Cout * Cin;
    for (long long i = (long long)blockIdx.x * blockDim.x + threadIdx.x; i < total;
         i += (long long)gridDim.x * blockDim.x) {
        int ci = (int)(i % Cin);
        long long t = i / Cin;
        int co = (int)(t % Cout);
        int blk = (int)(t / Cout);
        dst[((long long)blk * Cin + ci) * Cout + co] = src[i];
    }
}

// codebook [1024][256] -> cbT [256][1024]
__global__ void packT_k(const float* __restrict__ src, float* __restrict__ dst) {
    int i = blockIdx.x * blockDim.x + threadIdx.x;   // 262144 total
    if (i < 262144) {
        int d = i & 255, k = i >> 8;
        dst[d * 1024 + k] = src[i];
    }
}

__global__ void init_k(unsigned long long* bestkey, float* vqsum, float* reconsum) {
    int i = blockIdx.x * blockDim.x + threadIdx.x;
    if (i < 32768) bestkey[i] = 0xFFFFFFFFFFFFFFFFull;
    if (i == 0) { *vqsum = 0.f; *reconsum = 0.f; }
}

__global__ void cnorm_k(const float* __restrict__ cb, float* __restrict__ cn) {
    int k = blockIdx.x;          // 1024 blocks, 256 threads
    float v = cb[k * 256 + threadIdx.x];
    float p = warpReduceSum(v * v);
    __shared__ float sh[8];
    if ((threadIdx.x & 31) == 0) sh[threadIdx.x >> 5] = p;
    __syncthreads();
    if (threadIdx.x == 0) {
        float t = 0.f;
#pragma unroll
        for (int i = 0; i < 8; i++) t += sh[i];
        cn[k] = t;
    }
}

// per-pixel ||z||^2 over D=256 (z layout [B][256][64][64])
__global__ void znorm_k(const float* __restrict__ z, float* __restrict__ zn) {
    int n = blockIdx.x * blockDim.x + threadIdx.x;   // 32768
    if (n >= 32768) return;
    int b = n >> 12, rem = n & 4095;
    const float* zp = z + (((size_t)b * 256) << 12) + rem;
    float s = 0.f;
#pragma unroll 8
    for (int d = 0; d < 256; d++) {
        float v = zp[(size_t)d << 12];
        s = fmaf(v, v, s);
    }
    zn[n] = s;
}

// ------------------------------ conv0 (4x4 s2) ------------------------------
__global__ void conv0_k(const float* __restrict__ x, const float* __restrict__ w,
                        const float* __restrict__ bias, float* __restrict__ out) {
    int idx = blockIdx.x * blockDim.x + threadIdx.x;     // 8*256*64*64
    if (idx >= 8388608) return;
    int ox = idx & 63, oy = (idx >> 6) & 63, co = (idx >> 12) & 255, b = idx >> 20;
    float acc = bias[co];
    const float* wc = w + co * 48;
#pragma unroll
    for (int c = 0; c < 3; c++) {
        const float* xp = x + (size_t)(b * 3 + c) * 16384;
#pragma unroll
        for (int ky = 0; ky < 4; ky++) {
            int iy = oy * 2 - 1 + ky;
            if (iy < 0 || iy >= 128) continue;
#pragma unroll
            for (int kx = 0; kx < 4; kx++) {
                int ix = ox * 2 - 1 + kx;
                if (ix < 0 || ix >= 128) continue;
                acc = fmaf(xp[iy * 128 + ix], wc[c * 16 + ky * 4 + kx], acc);
            }
        }
    }
    out[idx] = acc;
}

// ------------------------------- batchnorm ----------------------------------
__global__ void bn_stats_k(const float* __restrict__ buf, const float* __restrict__ g,
                           const float* __restrict__ bb, int C,
                           float* __restrict__ scale, float* __restrict__ shift) {
    int c = blockIdx.x;
    int tid = threadIdx.x;
    double s = 0.0, s2 = 0.0;
    for (int t = tid; t < 8 * 4096; t += 256) {
        int b = t >> 12, off = t & 4095;
        float v = buf[(((size_t)b * C + c) << 12) + off];
        s += (double)v; s2 += (double)v * v;
    }
    __shared__ double sh[256], sh2[256];
    sh[tid] = s; sh2[tid] = s2;
    __syncthreads();
    for (int st = 128; st; st >>= 1) {
        if (tid < st) { sh[tid] += sh[tid + st]; sh2[tid] += sh2[tid + st]; }
        __syncthreads();
    }
    if (tid == 0) {
        double m = sh[0] / 32768.0;
        double v = sh2[0] / 32768.0 - m * m;
        double sc = (double)g[c] / sqrt(v + 1e-5);
        scale[c] = (float)sc;
        shift[c] = (float)((double)bb[c] - m * sc);
    }
}

__global__ void bn_apply_k(float* __restrict__ buf, const float* __restrict__ scale,
                           const float* __restrict__ shift, int C, int total) {
    int i = blockIdx.x * blockDim.x + threadIdx.x;
    if (i >= total) return;
    int c = (i >> 12) % C;
    buf[i] = fmaxf(fmaf(buf[i], scale[c], shift[c]), 0.f);
}

__global__ void relu_ip_k(float* __restrict__ buf, int total) {
    int i = blockIdx.x * blockDim.x + threadIdx.x;
    if (i < total) buf[i] = fmaxf(buf[i], 0.f);
}

// --------------------------- 3x3 conv (implicit GEMM) -----------------------
// Tile: 128 Cout x 64 pixels (one image row). 256 threads, 8x4 acc/thread.
// wp layout: [9][Cin][Cout]; in/out: [B][C][64][64].
template <bool RELU_IN, bool RELU_OUT>
__global__ void __launch_bounds__(256)
conv3x3_k(const float* __restrict__ in, const float* __restrict__ wp,
          const float* __restrict__ bias, float* __restrict__ out,
          int Cin, int Cout) {
    const int cout0 = blockIdx.x * 128;
    const int by = blockIdx.y;
    const int b = by >> 6, y = by & 63;
    const int tid = threadIdx.x;
    const int tx = tid & 15, ty = tid >> 4;

    __shared__ __align__(16) float Ws[16][128];
    __shared__ __align__(16) float Xs[16][64];

    float acc[8][4];
#pragma unroll
    for (int i = 0; i < 8; i++)
#pragma unroll
        for (int j = 0; j < 4; j++) acc[i][j] = 0.f;

    const int l = tid * 4;
    const int kW = l >> 7, coW = l & 127;        // + second slab at kW+8
    const int kX = l >> 6, pxX = l & 63;

    for (int r = 0; r < 9; ++r) {
        const int dy = r / 3 - 1, dx = r % 3 - 1;
        const int iy = y + dy;
        if (iy < 0 || iy >= 64) continue;        // uniform per block
        const float* wtap = wp + (size_t)r * Cin * Cout;
        const float* inrow = in + (size_t)b * Cin * 4096 + (size_t)iy * 64;
        for (int c0 = 0; c0 < Cin; c0 += 16) {
            __syncthreads();
            *(float4*)&Ws[kW][coW] =
                *(const float4*)(wtap + (size_t)(c0 + kW) * Cout + cout0 + coW);
            *(float4*)&Ws[kW + 8][coW] =
                *(const float4*)(wtap + (size_t)(c0 + kW + 8) * Cout + cout0 + coW);
            {
                const float* src = inrow + (size_t)(c0 + kX) * 4096;
#pragma unroll
                for (int j = 0; j < 4; j++) {
                    int xx = pxX + j + dx;
                    float v = (xx >= 0 && xx < 64) ? src[xx] : 0.f;
                    if (RELU_IN) v = fmaxf(v, 0.f);
                    Xs[kX][pxX + j] = v;
                }
            }
            __syncthreads();
#pragma unroll
            for (int k = 0; k < 16; k++) {
                const float4 bv = *(const float4*)&Xs[k][tx * 4];
                const float4 a0 = *(const float4*)&Ws[k][ty * 8];
                const float4 a1 = *(const float4*)&Ws[k][ty * 8 + 4];
                const float bj[4] = {bv.x, bv.y, bv.z, bv.w};
                const float ai[8] = {a0.x, a0.y, a0.z, a0.w, a1.x, a1.y, a1.z, a1.w};
#pragma unroll
                for (int i = 0; i < 8; i++)
#pragma unroll
                    for (int j = 0; j < 4; j++)
                        acc[i][j] = fmaf(ai[i], bj[j], acc[i][j]);
            }
        }
    }

#pragma unroll
    for (int i = 0; i < 8; i++) {
        const int co = cout0 + ty * 8 + i;
        const float bs = bias[co];
        float* orow = out + (((size_t)b * Cout + co) * 64 + y) * 64;
        float4 o4;
        o4.x = acc[i][0] + bs; o4.y = acc[i][1] + bs;
        o4.z = acc[i][2] + bs; o4.w = acc[i][3] + bs;
        if (RELU_OUT) {
            o4.x = fmaxf(o4.x, 0.f); o4.y = fmaxf(o4.y, 0.f);
            o4.z = fmaxf(o4.z, 0.f); o4.w = fmaxf(o4.w, 0.f);
        }
        *(float4*)(orow + tx * 4) = o4;
    }
}

// --------------------------- 1x1 conv + residual add ------------------------
__global__ void __launch_bounds__(256)
conv1x1_acc_k(const float* __restrict__ in, const float* __restrict__ wp,
              const float* __restrict__ bias, float* __restrict__ out,
              int Cin, int Cout) {
    const int cout0 = blockIdx.x * 128;
    const int by = blockIdx.y;
    const int b = by >> 6, y = by & 63;
    const int tid = threadIdx.x;
    const int tx = tid & 15, ty = tid >> 4;

    __shared__ __align__(16) float Ws[16][128];
    __shared__ __align__(16) float Xs[16][64];

    float acc[8][4];
#pragma unroll
    for (int i = 0; i < 8; i++)
#pragma unroll
        for (int j = 0; j < 4; j++) acc[i][j] = 0.f;

    const int l = tid * 4;
    const int kW = l >> 7, coW = l & 127;
    const int kX = l >> 6, pxX = l & 63;
    const float* inrow = in + (size_t)b * Cin * 4096 + (size_t)y * 64;

    for (int c0 = 0; c0 < Cin; c0 += 16) {
        __syncthreads();
        *(float4*)&Ws[kW][coW] =
            *(const float4*)(wp + (size_t)(c0 + kW) * Cout + cout0 + coW);
        *(float4*)&Ws[kW + 8][coW] =
            *(const float4*)(wp + (size_t)(c0 + kW + 8) * Cout + cout0 + coW);
        *(float4*)&Xs[kX][pxX] =
            *(const float4*)(inrow + (size_t)(c0 + kX) * 4096 + pxX);
        __syncthreads();
#pragma unroll
        for (int k = 0; k < 16; k++) {
            const float4 bv = *(const float4*)&Xs[k][tx * 4];
            const float4 a0 = *(const float4*)&Ws[k][ty * 8];
            const float4 a1 = *(const float4*)&Ws[k][ty * 8 + 4];
            const float bj[4] = {bv.x, bv.y, bv.z, bv.w};
            const float ai[8] = {a0.x, a0.y, a0.z, a0.w, a1.x, a1.y, a1.z, a1.w};
#pragma unroll
            for (int i = 0; i < 8; i++)
#pragma unroll
                for (int j = 0; j < 4; j++)
                    acc[i][j] = fmaf(ai[i], bj[j], acc[i][j]);
        }
    }

#pragma unroll
    for (int i = 0; i < 8; i++) {
        const int co = cout0 + ty * 8 + i;
        const float bs = bias[co];
        float* orow = out + (((size_t)b * Cout + co) * 64 + y) * 64;
        float4 cur = *(float4*)(orow + tx * 4);
        cur.x += acc[i][0] + bs; cur.y += acc[i][1] + bs;
        cur.z += acc[i][2] + bs; cur.w += acc[i][3] + bs;
        *(float4*)(orow + tx * 4) = cur;
    }
}

// ------------------------------- VQ argmin -----------------------------------
// Tile: 64 vectors (one row) x 64 codes; D=256 in chunks of 16.
// Score replicates the reference's fp32 rounding: (||z||^2 - 2*dot) + ||c||^2,
// so near-tie bucketing matches np.argmin (first-min tie-break via 64-bit key).
__global__ void __launch_bounds__(256)
vq_argmin_k(const float* __restrict__ z, const float* __restrict__ cbT,
            const float* __restrict__ cn, const float* __restrict__ zn,
            unsigned long long* __restrict__ bestkey) {
    const int code0 = blockIdx.x * 64;
    const int by = blockIdx.y;
    const int b = by >> 6, y = by & 63;
    const int tid = threadIdx.x;
    const int tx = tid & 15, ty = tid >> 4;

    __shared__ __align__(16) float Cs[16][64];
    __shared__ __align__(16) float Zs[16][64];
    __shared__ unsigned long long red[16][64];

    float acc[4][4];
#pragma unroll
    for (int i = 0; i < 4; i++)
#pragma unroll
        for (int j = 0; j < 4; j++) acc[i][j] = 0.f;

    const int l = tid * 4;
    const int k = l >> 6, c = l & 63;

    for (int d0 = 0; d0 < 256; d0 += 16) {
        __syncthreads();
        *(float4*)&Cs[k][c] = *(const float4*)&cbT[(size_t)(d0 + k) * 1024 + code0 + c];
        *(float4*)&Zs[k][c] =
            *(const float4*)&z[(((size_t)b * 256 + d0 + k) * 64 + y) * 64 + c];
        __syncthreads();
#pragma unroll
        for (int kk = 0; kk < 16; kk++) {
            const float4 av = *(const float4*)&Cs[kk][ty * 4];
            const float4 bv = *(const float4*)&Zs[kk][tx * 4];
            const float ai[4] = {av.x, av.y, av.z, av.w};
            const float bj[4] = {bv.x, bv.y, bv.z, bv.w};
#pragma unroll
            for (int i = 0; i < 4; i++)
#pragma unroll
                for (int j = 0; j < 4; j++)
                    acc[i][j] = fmaf(ai[i], bj[j], acc[i][j]);
        }
    }

#pragma unroll
    for (int j = 0; j < 4; j++) {
        const float znv = zn[by * 64 + tx * 4 + j];
        unsigned long long best = 0xFFFFFFFFFFFFFFFFull;
#pragma unroll
        for (int i = 0; i < 4; i++) {
            const int code = code0 + ty * 4 + i;
            // match reference rounding order: (znorm - 2*dot) + cnorm
            const float s = (znv - 2.f * acc[i][j]) + cn[code];
            unsigned int u = __float_as_uint(s);
            unsigned int k32 = (u >> 31) ? ~u : (u | 0x80000000u);
            unsigned long long key = ((unsigned long long)k32 << 32) | (unsigned int)code;
            best = (key < best) ? key : best;
        }
        red[ty][tx * 4 + j] = best;
    }
    __syncthreads();
    for (int st = 8; st; st >>= 1) {
        if (ty < st) {
#pragma unroll
            for (int j = 0; j < 4; j++) {
                unsigned long long a = red[ty][tx * 4 + j];
                unsigned long long b2 = red[ty + st][tx * 4 + j];
                red[ty][tx * 4 + j] = (b2 < a) ? b2 : a;
            }
        }
        __syncthreads();
    }
    if (ty == 0) {
#pragma unroll
        for (int j = 0; j < 4; j++)
            atomicMin(&bestkey[by * 64 + tx * 4 + j], red[0][tx * 4 + j]);
    }
}

// q gather + straight-through output + vq loss accumulation.
// Straight-through value is zf + (q - zf) in fp32 (NOT bitwise q) to match ref.
__global__ void vq_gather_k(const float* __restrict__ z, const float* __restrict__ cb,
                            const unsigned long long* __restrict__ bestkey,
                            float* __restrict__ zq, float* __restrict__ vqsum) {
    const int n = blockIdx.x;                 // 32768
    const int d = threadIdx.x;                // 256
    const int idx = (int)(bestkey[n] & 0xFFFFFFFFull);
    const int b = n >> 12, rem = n & 4095;
    const float q = cb[idx * 256 + d];
    const size_t zoff = (((size_t)b * 256 + d) << 12) + rem;
    const float zv = z[zoff];
    const float diff = q - zv;
    zq[zoff] = zv + diff;   // straight-through: zf + (q - zf), reference rounding
    float p = warpReduceSum(diff * diff);
    __shared__ float sh[8];
    if ((threadIdx.x & 31) == 0) sh[threadIdx.x >> 5] = p;
    __syncthreads();
    if (threadIdx.x == 0) {
        float t = 0.f;
#pragma unroll
        for (int i = 0; i < 8; i++) t += sh[i];
        atomicAdd(vqsum, t);
    }
}

// -------------------------------- deconv -------------------------------------
// ConvTranspose2d(256->3, k=4, s=2, p=1); fuses recon-loss partials.
__global__ void deconv_k(const float* __restrict__ in, const float* __restrict__ w,
                         const float* __restrict__ bias, const float* __restrict__ x,
                         float* __restrict__ out, float* __restrict__ reconsum) {
    const int idx = blockIdx.x * blockDim.x + threadIdx.x;   // 8*3*128*128
    if (idx >= 393216) return;
    const int ox = idx & 127, oy = (idx >> 7) & 127;
    const int bo = idx >> 14;
    const int o = bo % 3, b = bo / 3;
    float acc = bias[o];
    const int kyp = (oy + 1) & 1, kxp = (ox + 1) & 1;
#pragma unroll
    for (int t = 0; t < 4; t++) {
        const int ky = kyp + 2 * (t >> 1);
        const int kx = kxp + 2 * (t & 1);
        const int ny = oy + 1 - ky, nx = ox + 1 - kx;
        if (ny < 0 || nx < 0) continue;
        const int iy = ny >> 1, ix = nx >> 1;
        if (iy >= 64 || ix >= 64) continue;
        const float* ip = in + (size_t)b * 256 * 4096 + iy * 64 + ix;
        const float* wpp = w + o * 16 + ky * 4 + kx;
        float a = 0.f;
        for (int c2 = 0; c2 < 256; c2++)
            a = fmaf(ip[(size_t)c2 * 4096], wpp[c2 * 48], a);
        acc += a;
    }
    out[idx] = acc;
    const float d = acc - x[idx];
    float p = warpReduceSum(d * d);
    if ((threadIdx.x & 31) == 0) atomicAdd(reconsum, p);
}

__global__ void finalize_k(float* __restrict__ out, const float* __restrict__ vqsum,
                           const float* __restrict__ reconsum) {
    const float recon = *reconsum * (1.f / 393216.f);
    const float vq = 1.25f * (*vqsum) * (1.f / 8388608.f);
    out[393216] = recon + vq;
    out[393217] = recon;
}

// --------------------------------- launch ------------------------------------
extern "C" void kernel_launch(void* const* d_in, const int* in_sizes, int n_in,
                              void* d_out, int out_size) {
    const float* x          = (const float*)d_in[0];
    const float* ec0_w      = (const float*)d_in[1];
    const float* ec0_b      = (const float*)d_in[2];
    const float* ebn0_g     = (const float*)d_in[3];
    const float* ebn0_b     = (const float*)d_in[4];
    const float* ec1_w      = (const float*)d_in[5];
    const float* ec1_b      = (const float*)d_in[6];
    const float* ebn1_g     = (const float*)d_in[7];
    const float* ebn1_b     = (const float*)d_in[8];
    const float* ec2_w      = (const float*)d_in[9];
    const float* ec2_b      = (const float*)d_in[10];
    const float* er_w1      = (const float*)d_in[11];
    const float* er_b1      = (const float*)d_in[12];
    const float* er_w2      = (const float*)d_in[13];
    const float* er_b2      = (const float*)d_in[14];
    const float* ec3_w      = (const float*)d_in[15];
    const float* ec3_b      = (const float*)d_in[16];
    const float* codebook   = (const float*)d_in[17];
    const float* dc0_w      = (const float*)d_in[18];
    const float* dc0_b      = (const float*)d_in[19];
    const float* dr_w1      = (const float*)d_in[20];
    const float* dr_b1      = (const float*)d_in[21];
    const float* dr_w2      = (const float*)d_in[22];
    const float* dr_b2      = (const float*)d_in[23];
    const float* dc1_w      = (const float*)d_in[24];
    const float* dc1_b      = (const float*)d_in[25];
    const float* dd_w       = (const float*)d_in[26];
    const float* dd_b       = (const float*)d_in[27];
    float* out = (float*)d_out;

    float *bufA, *bufB, *bufT, *bufZ;
    float *pw1, *pw2, *pwE1, *pwE2, *pw3, *pwD0, *pwDr1, *pwDr2, *pwD1;
    float *cbT, *cn, *zn, *bnsc, *bnsh, *vqsum, *reconsum;
    unsigned long long* bestkey;
    cudaGetSymbolAddress((void**)&bufA, g_bufA);
    cudaGetSymbolAddress((void**)&bufB, g_bufB);
    cudaGetSymbolAddress((void**)&bufT, g_bufT);
    cudaGetSymbolAddress((void**)&bufZ, g_bufZ);
    cudaGetSymbolAddress((void**)&pw1,  g_pw1);
    cudaGetSymbolAddress((void**)&pw2,  g_pw2);
    cudaGetSymbolAddress((void**)&pwE1, g_pwE1);
    cudaGetSymbolAddress((void**)&pwE2, g_pwE2);
    cudaGetSymbolAddress((void**)&pw3,  g_pw3);
    cudaGetSymbolAddress((void**)&pwD0, g_pwD0);
    cudaGetSymbolAddress((void**)&pwDr1, g_pwDr1);
    cudaGetSymbolAddress((void**)&pwDr2, g_pwDr2);
    cudaGetSymbolAddress((void**)&pwD1, g_pwD1);
    cudaGetSymbolAddress((void**)&cbT,  g_cbT);
    cudaGetSymbolAddress((void**)&cn,   g_cnorm);
    cudaGetSymbolAddress((void**)&zn,   g_znorm);
    cudaGetSymbolAddress((void**)&bnsc, g_bnscale);
    cudaGetSymbolAddress((void**)&bnsh, g_bnshift);
    cudaGetSymbolAddress((void**)&vqsum, g_vqsum);
    cudaGetSymbolAddress((void**)&reconsum, g_reconsum);
    cudaGetSymbolAddress((void**)&bestkey, g_bestkey);

    // ---- weight repack + init ----
    pack3x3_k<<<4096, 256>>>(ec1_w, pw1, 1, 256, 512);
    pack3x3_k<<<4096, 256>>>(ec2_w, pw2, 1, 512, 512);
    pack3x3_k<<<8192, 256>>>(er_w1, pwE1, 16, 512, 128);
    pack1x1_k<<<2048, 256>>>(er_w2, pwE2, 16, 128, 512);
    pack3x3_k<<<4096, 256>>>(ec3_w, pw3, 1, 512, 256);
    pack3x3_k<<<4096, 256>>>(dc0_w, pwD0, 1, 256, 512);
    pack3x3_k<<<8192, 256>>>(dr_w1, pwDr1, 16, 512, 128);
    pack1x1_k<<<2048, 256>>>(dr_w2, pwDr2, 16, 128, 512);
    pack3x3_k<<<4096, 256>>>(dc1_w, pwD1, 1, 512, 256);
    packT_k<<<1024, 256>>>(codebook, cbT);
    init_k<<<128, 256>>>(bestkey, vqsum, reconsum);
    cnorm_k<<<1024, 256>>>(codebook, cn);

    // ---- encoder ----
    conv0_k<<<32768, 256>>>(x, ec0_w, ec0_b, bufZ);
    bn_stats_k<<<256, 256>>>(bufZ, ebn0_g, ebn0_b, 256, bnsc, bnsh);
    bn_apply_k<<<32768, 256>>>(bufZ, bnsc, bnsh, 256, 8 * 256 * 4096);

    conv3x3_k<false, false><<<dim3(4, BH), 256>>>(bufZ, pw1, ec1_b, bufA, 256, 512);
    bn_stats_k<<<512, 256>>>(bufA, ebn1_g, ebn1_b, 512, bnsc, bnsh);
    bn_apply_k<<<65536, 256>>>(bufA, bnsc, bnsh, 512, 8 * 512 * 4096);

    conv3x3_k<false, false><<<dim3(4, BH), 256>>>(bufA, pw2, ec2_b, bufB, 512, 512);

    for (int blk = 0; blk < 16; blk++) {
        conv3x3_k<true, true><<<dim3(1, BH), 256>>>(
            bufB, pwE1 + (size_t)blk * 9 * 512 * 128, er_b1 + blk * 128, bufT, 512, 128);
        conv1x1_acc_k<<<dim3(4, BH), 256>>>(
            bufT, pwE2 + (size_t)blk * 128 * 512, er_b2 + blk * 512, bufB, 128, 512);
        if ((blk & 3) == 3)
            relu_ip_k<<<65536, 256>>>(bufB, 8 * 512 * 4096);
    }

    conv3x3_k<false, false><<<dim3(2, BH), 256>>>(bufB, pw3, ec3_b, bufZ, 512, 256);

    // ---- vector quantizer ----
    znorm_k<<<128, 256>>>(bufZ, zn);
    vq_argmin_k<<<dim3(16, BH), 256>>>(bufZ, cbT, cn, zn, bestkey);
    vq_gather_k<<<32768, 256>>>(bufZ, codebook, bestkey, bufA, vqsum);

    // ---- decoder ----
    conv3x3_k<false, false><<<dim3(4, BH), 256>>>(bufA, pwD0, dc0_b, bufB, 256, 512);

    for (int blk = 0; blk < 16; blk++) {
        conv3x3_k<true, true><<<dim3(1, BH), 256>>>(
            bufB, pwDr1 + (size_t)blk * 9 * 512 * 128, dr_b1 + blk * 128, bufT, 512, 128);
        conv1x1_acc_k<<<dim3(4, BH), 256>>>(
            bufT, pwDr2 + (size_t)blk * 128 * 512, dr_b2 + blk * 512, bufB, 128, 512);
        if ((blk & 3) == 3)
            relu_ip_k<<<65536, 256>>>(bufB, 8 * 512 * 4096);
    }

    conv3x3_k<false, true><<<dim3(2, BH), 256>>>(bufB, pwD1, dc1_b, bufZ, 512, 256);

    deconv_k<<<1536, 256>>>(bufZ, dd_w, dd_b, x, out, reconsum);
    finalize_k<<<1, 1>>>(out, vqsum, reconsum);
}